// round 10
// baseline (speedup 1.0000x reference)
#include <cuda_runtime.h>
#include <math.h>
#include <mma.h>

using namespace nvcuda;

#define NN 50000
#define NN_PAD 50048   // 391 * 128
#define NE 800000
#define H 128
#define H3 384
#define NB 196         // scan blocks: 196*256 = 50176 >= NN

// ---------------- device scratch (no allocs allowed) ----------------
__device__ float g_h0[NN_PAD * H];
__device__ float g_h1[NN_PAD * H];
__device__ float g_hw[NN_PAD * H];
__device__ float g_gcn[NN_PAD * H];
__device__ float g_gi[NN_PAD * H3];
__device__ float g_gh[NN_PAD * H3];
__device__ float g_dinv[NN];
__device__ int   g_cnt[NN];
__device__ int   g_cur[NN];
__device__ int   g_rowptr[NN + 1];
__device__ int   g_bsum[256];
__device__ int2  g_edge[NE];

// ---------------- cp.async helpers ----------------
__device__ __forceinline__ void cp_async16(void* smem, const void* gmem, bool pred)
{
    unsigned saddr = (unsigned)__cvta_generic_to_shared(smem);
    int sz = pred ? 16 : 0;
    asm volatile("cp.async.cg.shared.global [%0], [%1], 16, %2;\n"
                 :: "r"(saddr), "l"(gmem), "r"(sz));
}
#define CP_COMMIT() asm volatile("cp.async.commit_group;\n" ::: "memory")
#define CP_WAIT0()  asm volatile("cp.async.wait_group 0;\n" ::: "memory")

// ---------------- tf32 tensor-core GEMM core (cp.async 2-stage) ----------------
#define ASTR 20    // 16 + 4 pad (80B rows, 16B aligned)
#define BSTR 132   // 128 + 4 pad (528B rows, 16B aligned)

__device__ __forceinline__ void tgemm_body(
    const float* __restrict__ A, const float* __restrict__ B,
    float* __restrict__ C, int M, int Ncol, int row0, int col0)
{
    __shared__ float As[2][128][ASTR];
    __shared__ float Bs[2][16][BSTR];
    const int tid = threadIdx.x;
    const int warp = tid >> 5;
    const int wr = warp >> 2;         // 0..1
    const int wc = warp & 3;          // 0..3

    wmma::fragment<wmma::accumulator, 16, 16, 8, float> acc[4][2];
#pragma unroll
    for (int i = 0; i < 4; i++)
#pragma unroll
        for (int j = 0; j < 2; j++)
            wmma::fill_fragment(acc[i][j], 0.0f);

    // prefetch helper: stage st, k-offset k0
    auto prefetch = [&](int k0, int st) {
#pragma unroll
        for (int t = 0; t < 2; t++) {           // A: 128x16 = 512 float4
            int idx = tid + t * 256;
            int r = idx >> 2;
            int q = idx & 3;
            int gr = row0 + r;
            bool p = gr < M;
            const float* src = A + (size_t)(p ? gr : 0) * 128 + k0 + q * 4;
            cp_async16(&As[st][r][q * 4], src, p);
        }
#pragma unroll
        for (int t = 0; t < 2; t++) {           // B: 16x128 = 512 float4
            int idx = tid + t * 256;
            int r = idx >> 5;
            int q = idx & 31;
            cp_async16(&Bs[st][r][q * 4], &B[(size_t)(k0 + r) * Ncol + col0 + q * 4], true);
        }
    };

    prefetch(0, 0);
    CP_COMMIT();

#pragma unroll
    for (int kt = 0; kt < 8; kt++) {
        int st = kt & 1;
        CP_WAIT0();
        __syncthreads();
        if (kt < 7) {
            prefetch((kt + 1) * 16, st ^ 1);
            CP_COMMIT();
        }
#pragma unroll
        for (int kk = 0; kk < 16; kk += 8) {
            wmma::fragment<wmma::matrix_a, 16, 16, 8, wmma::precision::tf32, wmma::row_major> af[4];
            wmma::fragment<wmma::matrix_b, 16, 16, 8, wmma::precision::tf32, wmma::row_major> bf[2];
#pragma unroll
            for (int i = 0; i < 4; i++)
                wmma::load_matrix_sync(af[i], &As[st][wr * 64 + i * 16][kk], ASTR);
#pragma unroll
            for (int j = 0; j < 2; j++)
                wmma::load_matrix_sync(bf[j], &Bs[st][kk][wc * 32 + j * 16], BSTR);
#pragma unroll
            for (int i = 0; i < 4; i++)
#pragma unroll
                for (int j = 0; j < 2; j++)
                    wmma::mma_sync(acc[i][j], af[i], bf[j], acc[i][j]);
        }
    }

#pragma unroll
    for (int i = 0; i < 4; i++)
#pragma unroll
        for (int j = 0; j < 2; j++) {
            int r = row0 + wr * 64 + i * 16;
            int c = col0 + wc * 32 + j * 16;
            wmma::store_matrix_sync(&C[(size_t)r * Ncol + c], acc[i][j], Ncol, wmma::mem_row_major);
        }
}

__global__ void __launch_bounds__(256, 2) tgemm_k(
    const float* __restrict__ A, const float* __restrict__ B,
    float* __restrict__ C, int M, int Ncol)
{
    tgemm_body(A, B, C, M, Ncol, blockIdx.y * 128, blockIdx.x * 128);
}

// two independent GEMMs in one launch (blockIdx.z selects)
__global__ void __launch_bounds__(256, 2) tgemm2_k(
    const float* __restrict__ A0, const float* __restrict__ B0, float* __restrict__ C0,
    const float* __restrict__ A1, const float* __restrict__ B1, float* __restrict__ C1,
    int M, int Ncol)
{
    if (blockIdx.z == 0)
        tgemm_body(A0, B0, C0, M, Ncol, blockIdx.y * 128, blockIdx.x * 128);
    else
        tgemm_body(A1, B1, C1, M, Ncol, blockIdx.y * 128, blockIdx.x * 128);
}

// in-place bias + leaky relu over [NN, 128]
__global__ void biasact_k(float* __restrict__ p, const float* __restrict__ bias)
{
    int i = blockIdx.x * blockDim.x + threadIdx.x;
    if (i >= NN * H / 4) return;
    int c4 = i & (H / 4 - 1);
    float4 v = reinterpret_cast<float4*>(p)[i];
    float4 b = reinterpret_cast<const float4*>(bias)[c4];
    v.x += b.x; v.y += b.y; v.z += b.z; v.w += b.w;
    v.x = v.x >= 0.f ? v.x : 0.01f * v.x;
    v.y = v.y >= 0.f ? v.y : 0.01f * v.y;
    v.z = v.z >= 0.f ? v.z : 0.01f * v.z;
    v.w = v.w >= 0.f ? v.w : 0.01f * v.w;
    reinterpret_cast<float4*>(p)[i] = v;
}

// ---------------- CSR build ----------------
__global__ void zero_int_k(int* __restrict__ p, int n)
{
    int i = blockIdx.x * blockDim.x + threadIdx.x;
    if (i < n) p[i] = 0;
}

__global__ void count_k(const int* __restrict__ dst, int* __restrict__ cnt)
{
    int i = blockIdx.x * blockDim.x + threadIdx.x;
    if (i < NE) {
        int d = dst[i];
        if ((unsigned)d < NN) atomicAdd(&cnt[d], 1);
    }
}

// block partial sums (coalesced)
__global__ void __launch_bounds__(256) partial_k(const int* __restrict__ cnt,
                                                 int* __restrict__ bsum)
{
    int b = blockIdx.x, t = threadIdx.x;
    int i = b * 256 + t;
    int v = (i < NN) ? cnt[i] : 0;
#pragma unroll
    for (int o = 16; o; o >>= 1) v += __shfl_xor_sync(0xFFFFFFFFu, v, o);
    __shared__ int ws[8];
    if ((t & 31) == 0) ws[t >> 5] = v;
    __syncthreads();
    if (t == 0) {
        int s = 0;
#pragma unroll
        for (int w = 0; w < 8; w++) s += ws[w];
        bsum[b] = s;
    }
}

// single-block exclusive scan over NB partials (in-place)
__global__ void __launch_bounds__(256) scanb_k(int* __restrict__ bsum)
{
    __shared__ int s[256];
    int t = threadIdx.x;
    int v = (t < NB) ? bsum[t] : 0;
    s[t] = v;
    __syncthreads();
    for (int off = 1; off < 256; off <<= 1) {
        int u = (t >= off) ? s[t - off] : 0;
        __syncthreads();
        s[t] += u;
        __syncthreads();
    }
    bsum[t] = s[t] - v;   // exclusive
}

// per-block rescan: rowptr + cursor + dinv fused
__global__ void __launch_bounds__(256) rowptr_k(const int* __restrict__ cnt,
                                                const int* __restrict__ bsum,
                                                int* __restrict__ rowptr,
                                                int* __restrict__ cur,
                                                float* __restrict__ dinv)
{
    __shared__ int s[256];
    int b = blockIdx.x, t = threadIdx.x;
    int i = b * 256 + t;
    int v = (i < NN) ? cnt[i] : 0;
    s[t] = v;
    __syncthreads();
    for (int off = 1; off < 256; off <<= 1) {
        int u = (t >= off) ? s[t - off] : 0;
        __syncthreads();
        s[t] += u;
        __syncthreads();
    }
    int base = bsum[b];
    if (i < NN) {
        int rp = base + s[t] - v;
        rowptr[i] = rp;
        cur[i] = rp;
        dinv[i] = rsqrtf((float)v + 1.0f);
    }
    if (b == NB - 1 && t == 255) rowptr[NN] = base + s[t];
}

__global__ void fill_k(const int* __restrict__ src, const int* __restrict__ dst,
                       const float* __restrict__ dinv, int* __restrict__ cur,
                       int2* __restrict__ edge)
{
    int i = blockIdx.x * blockDim.x + threadIdx.x;
    if (i >= NE) return;
    int s = src[i], d = dst[i];
    if ((unsigned)s >= NN || (unsigned)d >= NN) return;
    float nrm = dinv[s] * dinv[d];
    int pos = atomicAdd(&cur[d], 1);
    edge[pos] = make_int2(s, __float_as_int(nrm));
}

// ---------------- fused aggregate + self-loop + bias + lrelu ----------------
__global__ void __launch_bounds__(256) agg_k(
    const int* __restrict__ rowptr, const int2* __restrict__ edge,
    const float* __restrict__ hw, const float* __restrict__ dinv,
    const float* __restrict__ bias, float* __restrict__ out)
{
    int warp = (blockIdx.x * blockDim.x + threadIdx.x) >> 5;
    int lane = threadIdx.x & 31;
    if (warp >= NN) return;
    int beg = rowptr[warp], end = rowptr[warp + 1];
    float di = dinv[warp];
    float d2 = di * di;
    float4 self = reinterpret_cast<const float4*>(&hw[(size_t)warp * H])[lane];
    float4 acc;
    acc.x = self.x * d2; acc.y = self.y * d2; acc.z = self.z * d2; acc.w = self.w * d2;
    for (int e = beg; e < end; e++) {
        int2 ed = __ldg(&edge[e]);
        float nrm = __int_as_float(ed.y);
        float4 v = __ldg(&reinterpret_cast<const float4*>(&hw[(size_t)ed.x * H])[lane]);
        acc.x = fmaf(v.x, nrm, acc.x);
        acc.y = fmaf(v.y, nrm, acc.y);
        acc.z = fmaf(v.z, nrm, acc.z);
        acc.w = fmaf(v.w, nrm, acc.w);
    }
    float4 b = reinterpret_cast<const float4*>(bias)[lane];
    acc.x += b.x; acc.y += b.y; acc.z += b.z; acc.w += b.w;
    acc.x = acc.x >= 0.f ? acc.x : 0.01f * acc.x;
    acc.y = acc.y >= 0.f ? acc.y : 0.01f * acc.y;
    acc.z = acc.z >= 0.f ? acc.z : 0.01f * acc.z;
    acc.w = acc.w >= 0.f ? acc.w : 0.01f * acc.w;
    reinterpret_cast<float4*>(&out[(size_t)warp * H])[lane] = acc;
}

// ---------------- GRU (biases folded) + head ----------------
__device__ __forceinline__ float sigm(float x) { return 1.0f / (1.0f + expf(-x)); }

__global__ void gru_k(const float* __restrict__ gi, const float* __restrict__ gh,
                      const float* __restrict__ bih, const float* __restrict__ bhh,
                      const float* __restrict__ prev, float* __restrict__ out)
{
    int i = blockIdx.x * blockDim.x + threadIdx.x;
    if (i >= NN * H) return;
    int nrow = i / H;
    int c = i % H;
    size_t base = (size_t)nrow * H3 + c;
    float ir = gi[base]          + bih[c];
    float iz = gi[base + H]      + bih[c + H];
    float inn = gi[base + 2 * H] + bih[c + 2 * H];
    float hr = gh[base]          + bhh[c];
    float hz = gh[base + H]      + bhh[c + H];
    float hn = gh[base + 2 * H]  + bhh[c + 2 * H];
    float r = sigm(ir + hr);
    float z = sigm(iz + hz);
    float nn_ = tanhf(inn + r * hn);
    out[i] = (1.0f - z) * nn_ + z * prev[i];
}

__global__ void post_k(const float* __restrict__ h, const float* __restrict__ w,
                       const float* __restrict__ b, float* __restrict__ out)
{
    int gwarp = (blockIdx.x * blockDim.x + threadIdx.x) >> 5;
    int lane = threadIdx.x & 31;
    if (gwarp >= NN) return;
    float4 wv = reinterpret_cast<const float4*>(w)[lane];
    float4 hv = reinterpret_cast<const float4*>(&h[(size_t)gwarp * H])[lane];
    float s = hv.x * wv.x + hv.y * wv.y + hv.z * wv.z + hv.w * wv.w;
#pragma unroll
    for (int o = 16; o; o >>= 1) s += __shfl_xor_sync(0xFFFFFFFFu, s, o);
    if (lane == 0) out[gwarp] = s + b[0];
}

// ---------------- launch ----------------
extern "C" void kernel_launch(void* const* d_in, const int* in_sizes, int n_in,
                              void* d_out, int out_size)
{
    const float* x        = (const float*)d_in[0];
    const int*   ei       = (const int*)d_in[1];
    const float* w_pre1   = (const float*)d_in[2];
    const float* b_pre1   = (const float*)d_in[3];
    const float* w_pre2   = (const float*)d_in[4];
    const float* b_pre2   = (const float*)d_in[5];
    const float* w_gcn0   = (const float*)d_in[6];
    const float* b_gcn0   = (const float*)d_in[7];
    const float* w_gcn1   = (const float*)d_in[8];
    const float* b_gcn1   = (const float*)d_in[9];
    const float* wih0     = (const float*)d_in[10];
    const float* whh0     = (const float*)d_in[11];
    const float* bih0     = (const float*)d_in[12];
    const float* bhh0     = (const float*)d_in[13];
    const float* wih1     = (const float*)d_in[14];
    const float* whh1     = (const float*)d_in[15];
    const float* bih1     = (const float*)d_in[16];
    const float* bhh1     = (const float*)d_in[17];
    const float* prev0    = (const float*)d_in[18];
    const float* prev1    = (const float*)d_in[19];
    const float* w_post   = (const float*)d_in[20];
    const float* b_post   = (const float*)d_in[21];

    float* out  = (float*)d_out;
    float* emb0 = out + NN;
    float* emb1 = emb0 + (size_t)NN * H;

    float *h0, *h1, *hw, *gcn, *gi, *gh, *dinv;
    int *cnt, *cur, *rowptr, *bsum;
    int2 *edge;
    cudaGetSymbolAddress((void**)&h0, g_h0);
    cudaGetSymbolAddress((void**)&h1, g_h1);
    cudaGetSymbolAddress((void**)&hw, g_hw);
    cudaGetSymbolAddress((void**)&gcn, g_gcn);
    cudaGetSymbolAddress((void**)&gi, g_gi);
    cudaGetSymbolAddress((void**)&gh, g_gh);
    cudaGetSymbolAddress((void**)&dinv, g_dinv);
    cudaGetSymbolAddress((void**)&cnt, g_cnt);
    cudaGetSymbolAddress((void**)&cur, g_cur);
    cudaGetSymbolAddress((void**)&rowptr, g_rowptr);
    cudaGetSymbolAddress((void**)&bsum, g_bsum);
    cudaGetSymbolAddress((void**)&edge, g_edge);

    const int* e_src = ei;
    const int* e_dst = ei + NE;

    dim3 g128(1, NN_PAD / 128);
    dim3 g384x2(3, NN_PAD / 128, 2);
    const int T = 256;

    // CSR build
    zero_int_k<<<(NN + T - 1) / T, T>>>(cnt, NN);
    count_k<<<(NE + T - 1) / T, T>>>(e_dst, cnt);
    partial_k<<<NB, 256>>>(cnt, bsum);
    scanb_k<<<1, 256>>>(bsum);
    rowptr_k<<<NB, 256>>>(cnt, bsum, rowptr, cur, dinv);
    fill_k<<<(NE + T - 1) / T, T>>>(e_src, e_dst, dinv, cur, edge);

    // pre MLP
    tgemm_k<<<g128, T>>>(x, w_pre1, h0, NN, H);
    biasact_k<<<(NN * H / 4 + T - 1) / T, T>>>(h0, b_pre1);
    tgemm_k<<<g128, T>>>(h0, w_pre2, h1, NN, H);
    biasact_k<<<(NN * H / 4 + T - 1) / T, T>>>(h1, b_pre2);

    // ---- layer 0 ----
    tgemm_k<<<g128, T>>>(h1, w_gcn0, hw, NN, H);
    agg_k<<<(NN * 32 + T - 1) / T, T>>>(rowptr, edge, hw, dinv, b_gcn0, gcn);
    tgemm2_k<<<g384x2, T>>>(gcn, wih0, gi, prev0, whh0, gh, NN, H3);
    gru_k<<<(NN * H + T - 1) / T, T>>>(gi, gh, bih0, bhh0, prev0, emb0);

    // ---- layer 1 ----
    tgemm_k<<<g128, T>>>(emb0, w_gcn1, hw, NN, H);
    agg_k<<<(NN * 32 + T - 1) / T, T>>>(rowptr, edge, hw, dinv, b_gcn1, gcn);
    tgemm2_k<<<g384x2, T>>>(gcn, wih1, gi, prev1, whh1, gh, NN, H3);
    gru_k<<<(NN * H + T - 1) / T, T>>>(gi, gh, bih1, bhh1, prev1, emb1);

    // post head
    post_k<<<(NN * 32 + T - 1) / T, T>>>(emb1, w_post, b_post, out);
}

// round 11
// speedup vs baseline: 1.3742x; 1.3742x over previous
#include <cuda_runtime.h>
#include <math.h>
#include <mma.h>

using namespace nvcuda;

#define NN 50000
#define NN_PAD 50048   // 391 * 128
#define NE 800000
#define H 128
#define H3 384
#define NB 196         // scan blocks: 196*256 = 50176 >= NN

// ---------------- device scratch (no allocs allowed) ----------------
__device__ float g_h0[NN_PAD * H];
__device__ float g_h1[NN_PAD * H];
__device__ float g_hw[NN_PAD * H];
__device__ float g_gcn[NN_PAD * H];
__device__ float g_gi[NN_PAD * H3];
__device__ float g_gh[NN_PAD * H3];
__device__ float g_dinv[NN];
__device__ int   g_cnt[NN];
__device__ int   g_cur[NN];
__device__ int   g_rowptr[NN + 1];
__device__ int   g_bsum[256];
__device__ int2  g_edge[NE];

// ---------------- tf32 tensor-core GEMM (R9-proven): C = A[M,128] @ B[128,Ncol] ----------------
// BM=128, BN=128, BK=32, 256 threads (8 warps, 2x4), warp tile 64x32.
#define ASTR 36
#define BSTR 132
__device__ __forceinline__ void tgemm_body(
    const float* __restrict__ A, const float* __restrict__ B,
    float* __restrict__ C, int M, int Ncol, int row0, int col0)
{
    __shared__ float As[128][ASTR];   // [row][k]
    __shared__ float Bs[32][BSTR];    // [k][col]
    const int tid = threadIdx.x;
    const int warp = tid >> 5;
    const int wr = warp >> 2;         // 0..1
    const int wc = warp & 3;          // 0..3

    wmma::fragment<wmma::accumulator, 16, 16, 8, float> acc[4][2];
#pragma unroll
    for (int i = 0; i < 4; i++)
#pragma unroll
        for (int j = 0; j < 2; j++)
            wmma::fill_fragment(acc[i][j], 0.0f);

    for (int k0 = 0; k0 < 128; k0 += 32) {
        // load A tile 128x32 (guarded rows, tf32 round-to-nearest)
#pragma unroll
        for (int t = 0; t < 4; t++) {
            int idx = tid + t * 256;
            int r = idx >> 3;
            int c = (idx & 7) << 2;
            float4 v = make_float4(0.f, 0.f, 0.f, 0.f);
            int gr = row0 + r;
            if (gr < M)
                v = *reinterpret_cast<const float4*>(&A[(size_t)gr * 128 + k0 + c]);
            As[r][c + 0] = wmma::__float_to_tf32(v.x);
            As[r][c + 1] = wmma::__float_to_tf32(v.y);
            As[r][c + 2] = wmma::__float_to_tf32(v.z);
            As[r][c + 3] = wmma::__float_to_tf32(v.w);
        }
        // load B tile 32x128
#pragma unroll
        for (int t = 0; t < 4; t++) {
            int idx = tid + t * 256;
            int r = idx >> 5;
            int c = (idx & 31) << 2;
            float4 v = *reinterpret_cast<const float4*>(&B[(size_t)(k0 + r) * Ncol + col0 + c]);
            Bs[r][c + 0] = wmma::__float_to_tf32(v.x);
            Bs[r][c + 1] = wmma::__float_to_tf32(v.y);
            Bs[r][c + 2] = wmma::__float_to_tf32(v.z);
            Bs[r][c + 3] = wmma::__float_to_tf32(v.w);
        }
        __syncthreads();
#pragma unroll
        for (int kk = 0; kk < 32; kk += 8) {
            wmma::fragment<wmma::matrix_a, 16, 16, 8, wmma::precision::tf32, wmma::row_major> af[4];
            wmma::fragment<wmma::matrix_b, 16, 16, 8, wmma::precision::tf32, wmma::row_major> bf[2];
#pragma unroll
            for (int i = 0; i < 4; i++)
                wmma::load_matrix_sync(af[i], &As[wr * 64 + i * 16][kk], ASTR);
#pragma unroll
            for (int j = 0; j < 2; j++)
                wmma::load_matrix_sync(bf[j], &Bs[kk][wc * 32 + j * 16], BSTR);
#pragma unroll
            for (int i = 0; i < 4; i++)
#pragma unroll
                for (int j = 0; j < 2; j++)
                    wmma::mma_sync(acc[i][j], af[i], bf[j], acc[i][j]);
        }
        __syncthreads();
    }

    // direct store (outputs padded to NN_PAD rows)
#pragma unroll
    for (int i = 0; i < 4; i++)
#pragma unroll
        for (int j = 0; j < 2; j++) {
            int r = row0 + wr * 64 + i * 16;
            int c = col0 + wc * 32 + j * 16;
            wmma::store_matrix_sync(&C[(size_t)r * Ncol + c], acc[i][j], Ncol, wmma::mem_row_major);
        }
}

__global__ void __launch_bounds__(256, 2) tgemm_k(
    const float* __restrict__ A, const float* __restrict__ B,
    float* __restrict__ C, int M, int Ncol)
{
    tgemm_body(A, B, C, M, Ncol, blockIdx.y * 128, blockIdx.x * 128);
}

// two independent GEMMs in one launch (blockIdx.z selects)
__global__ void __launch_bounds__(256, 2) tgemm2_k(
    const float* __restrict__ A0, const float* __restrict__ B0, float* __restrict__ C0,
    const float* __restrict__ A1, const float* __restrict__ B1, float* __restrict__ C1,
    int M, int Ncol)
{
    if (blockIdx.z == 0)
        tgemm_body(A0, B0, C0, M, Ncol, blockIdx.y * 128, blockIdx.x * 128);
    else
        tgemm_body(A1, B1, C1, M, Ncol, blockIdx.y * 128, blockIdx.x * 128);
}

// in-place bias + leaky relu over [NN, 128]
__global__ void biasact_k(float* __restrict__ p, const float* __restrict__ bias)
{
    int i = blockIdx.x * blockDim.x + threadIdx.x;
    if (i >= NN * H / 4) return;
    int c4 = i & (H / 4 - 1);
    float4 v = reinterpret_cast<float4*>(p)[i];
    float4 b = reinterpret_cast<const float4*>(bias)[c4];
    v.x += b.x; v.y += b.y; v.z += b.z; v.w += b.w;
    v.x = v.x >= 0.f ? v.x : 0.01f * v.x;
    v.y = v.y >= 0.f ? v.y : 0.01f * v.y;
    v.z = v.z >= 0.f ? v.z : 0.01f * v.z;
    v.w = v.w >= 0.f ? v.w : 0.01f * v.w;
    reinterpret_cast<float4*>(p)[i] = v;
}

// ---------------- CSR build ----------------
__global__ void zero_int_k(int* __restrict__ p, int n)
{
    int i = blockIdx.x * blockDim.x + threadIdx.x;
    if (i < n) p[i] = 0;
}

__global__ void count_k(const int* __restrict__ dst, int* __restrict__ cnt)
{
    int i = blockIdx.x * blockDim.x + threadIdx.x;
    if (i < NE) {
        int d = dst[i];
        if ((unsigned)d < NN) atomicAdd(&cnt[d], 1);
    }
}

// block partial sums (coalesced)
__global__ void __launch_bounds__(256) partial_k(const int* __restrict__ cnt,
                                                 int* __restrict__ bsum)
{
    int b = blockIdx.x, t = threadIdx.x;
    int i = b * 256 + t;
    int v = (i < NN) ? cnt[i] : 0;
#pragma unroll
    for (int o = 16; o; o >>= 1) v += __shfl_xor_sync(0xFFFFFFFFu, v, o);
    __shared__ int ws[8];
    if ((t & 31) == 0) ws[t >> 5] = v;
    __syncthreads();
    if (t == 0) {
        int s = 0;
#pragma unroll
        for (int w = 0; w < 8; w++) s += ws[w];
        bsum[b] = s;
    }
}

// single-block exclusive scan over NB partials (in-place)
__global__ void __launch_bounds__(256) scanb_k(int* __restrict__ bsum)
{
    __shared__ int s[256];
    int t = threadIdx.x;
    int v = (t < NB) ? bsum[t] : 0;
    s[t] = v;
    __syncthreads();
    for (int off = 1; off < 256; off <<= 1) {
        int u = (t >= off) ? s[t - off] : 0;
        __syncthreads();
        s[t] += u;
        __syncthreads();
    }
    bsum[t] = s[t] - v;   // exclusive
}

// per-block rescan: rowptr + cursor + dinv fused
__global__ void __launch_bounds__(256) rowptr_k(const int* __restrict__ cnt,
                                                const int* __restrict__ bsum,
                                                int* __restrict__ rowptr,
                                                int* __restrict__ cur,
                                                float* __restrict__ dinv)
{
    __shared__ int s[256];
    int b = blockIdx.x, t = threadIdx.x;
    int i = b * 256 + t;
    int v = (i < NN) ? cnt[i] : 0;
    s[t] = v;
    __syncthreads();
    for (int off = 1; off < 256; off <<= 1) {
        int u = (t >= off) ? s[t - off] : 0;
        __syncthreads();
        s[t] += u;
        __syncthreads();
    }
    int base = bsum[b];
    if (i < NN) {
        int rp = base + s[t] - v;
        rowptr[i] = rp;
        cur[i] = rp;
        dinv[i] = rsqrtf((float)v + 1.0f);
    }
    if (b == NB - 1 && t == 255) rowptr[NN] = base + s[t];
}

__global__ void fill_k(const int* __restrict__ src, const int* __restrict__ dst,
                       const float* __restrict__ dinv, int* __restrict__ cur,
                       int2* __restrict__ edge)
{
    int i = blockIdx.x * blockDim.x + threadIdx.x;
    if (i >= NE) return;
    int s = src[i], d = dst[i];
    if ((unsigned)s >= NN || (unsigned)d >= NN) return;
    float nrm = dinv[s] * dinv[d];
    int pos = atomicAdd(&cur[d], 1);
    edge[pos] = make_int2(s, __float_as_int(nrm));
}

// ---------------- fused aggregate + self-loop + bias + lrelu ----------------
__global__ void __launch_bounds__(256) agg_k(
    const int* __restrict__ rowptr, const int2* __restrict__ edge,
    const float* __restrict__ hw, const float* __restrict__ dinv,
    const float* __restrict__ bias, float* __restrict__ out)
{
    int warp = (blockIdx.x * blockDim.x + threadIdx.x) >> 5;
    int lane = threadIdx.x & 31;
    if (warp >= NN) return;
    int beg = rowptr[warp], end = rowptr[warp + 1];
    float di = dinv[warp];
    float d2 = di * di;
    float4 self = reinterpret_cast<const float4*>(&hw[(size_t)warp * H])[lane];
    float4 acc;
    acc.x = self.x * d2; acc.y = self.y * d2; acc.z = self.z * d2; acc.w = self.w * d2;
    for (int e = beg; e < end; e++) {
        int2 ed = __ldg(&edge[e]);
        float nrm = __int_as_float(ed.y);
        float4 v = __ldg(&reinterpret_cast<const float4*>(&hw[(size_t)ed.x * H])[lane]);
        acc.x = fmaf(v.x, nrm, acc.x);
        acc.y = fmaf(v.y, nrm, acc.y);
        acc.z = fmaf(v.z, nrm, acc.z);
        acc.w = fmaf(v.w, nrm, acc.w);
    }
    float4 b = reinterpret_cast<const float4*>(bias)[lane];
    acc.x += b.x; acc.y += b.y; acc.z += b.z; acc.w += b.w;
    acc.x = acc.x >= 0.f ? acc.x : 0.01f * acc.x;
    acc.y = acc.y >= 0.f ? acc.y : 0.01f * acc.y;
    acc.z = acc.z >= 0.f ? acc.z : 0.01f * acc.z;
    acc.w = acc.w >= 0.f ? acc.w : 0.01f * acc.w;
    reinterpret_cast<float4*>(&out[(size_t)warp * H])[lane] = acc;
}

// ---------------- GRU (biases folded) + head ----------------
__device__ __forceinline__ float sigm(float x) { return 1.0f / (1.0f + expf(-x)); }

__global__ void gru_k(const float* __restrict__ gi, const float* __restrict__ gh,
                      const float* __restrict__ bih, const float* __restrict__ bhh,
                      const float* __restrict__ prev, float* __restrict__ out)
{
    int i = blockIdx.x * blockDim.x + threadIdx.x;
    if (i >= NN * H) return;
    int nrow = i / H;
    int c = i % H;
    size_t base = (size_t)nrow * H3 + c;
    float ir = gi[base]          + bih[c];
    float iz = gi[base + H]      + bih[c + H];
    float inn = gi[base + 2 * H] + bih[c + 2 * H];
    float hr = gh[base]          + bhh[c];
    float hz = gh[base + H]      + bhh[c + H];
    float hn = gh[base + 2 * H]  + bhh[c + 2 * H];
    float r = sigm(ir + hr);
    float z = sigm(iz + hz);
    float nn_ = tanhf(inn + r * hn);
    out[i] = (1.0f - z) * nn_ + z * prev[i];
}

__global__ void post_k(const float* __restrict__ h, const float* __restrict__ w,
                       const float* __restrict__ b, float* __restrict__ out)
{
    int gwarp = (blockIdx.x * blockDim.x + threadIdx.x) >> 5;
    int lane = threadIdx.x & 31;
    if (gwarp >= NN) return;
    float4 wv = reinterpret_cast<const float4*>(w)[lane];
    float4 hv = reinterpret_cast<const float4*>(&h[(size_t)gwarp * H])[lane];
    float s = hv.x * wv.x + hv.y * wv.y + hv.z * wv.z + hv.w * wv.w;
#pragma unroll
    for (int o = 16; o; o >>= 1) s += __shfl_xor_sync(0xFFFFFFFFu, s, o);
    if (lane == 0) out[gwarp] = s + b[0];
}

// ---------------- launch ----------------
extern "C" void kernel_launch(void* const* d_in, const int* in_sizes, int n_in,
                              void* d_out, int out_size)
{
    const float* x        = (const float*)d_in[0];
    const int*   ei       = (const int*)d_in[1];
    const float* w_pre1   = (const float*)d_in[2];
    const float* b_pre1   = (const float*)d_in[3];
    const float* w_pre2   = (const float*)d_in[4];
    const float* b_pre2   = (const float*)d_in[5];
    const float* w_gcn0   = (const float*)d_in[6];
    const float* b_gcn0   = (const float*)d_in[7];
    const float* w_gcn1   = (const float*)d_in[8];
    const float* b_gcn1   = (const float*)d_in[9];
    const float* wih0     = (const float*)d_in[10];
    const float* whh0     = (const float*)d_in[11];
    const float* bih0     = (const float*)d_in[12];
    const float* bhh0     = (const float*)d_in[13];
    const float* wih1     = (const float*)d_in[14];
    const float* whh1     = (const float*)d_in[15];
    const float* bih1     = (const float*)d_in[16];
    const float* bhh1     = (const float*)d_in[17];
    const float* prev0    = (const float*)d_in[18];
    const float* prev1    = (const float*)d_in[19];
    const float* w_post   = (const float*)d_in[20];
    const float* b_post   = (const float*)d_in[21];

    float* out  = (float*)d_out;
    float* emb0 = out + NN;
    float* emb1 = emb0 + (size_t)NN * H;

    float *h0, *h1, *hw, *gcn, *gi, *gh, *dinv;
    int *cnt, *cur, *rowptr, *bsum;
    int2 *edge;
    cudaGetSymbolAddress((void**)&h0, g_h0);
    cudaGetSymbolAddress((void**)&h1, g_h1);
    cudaGetSymbolAddress((void**)&hw, g_hw);
    cudaGetSymbolAddress((void**)&gcn, g_gcn);
    cudaGetSymbolAddress((void**)&gi, g_gi);
    cudaGetSymbolAddress((void**)&gh, g_gh);
    cudaGetSymbolAddress((void**)&dinv, g_dinv);
    cudaGetSymbolAddress((void**)&cnt, g_cnt);
    cudaGetSymbolAddress((void**)&cur, g_cur);
    cudaGetSymbolAddress((void**)&rowptr, g_rowptr);
    cudaGetSymbolAddress((void**)&bsum, g_bsum);
    cudaGetSymbolAddress((void**)&edge, g_edge);

    const int* e_src = ei;
    const int* e_dst = ei + NE;

    dim3 g128(1, NN_PAD / 128);
    dim3 g384x2(3, NN_PAD / 128, 2);
    const int T = 256;

    // CSR build
    zero_int_k<<<(NN + T - 1) / T, T>>>(cnt, NN);
    count_k<<<(NE + T - 1) / T, T>>>(e_dst, cnt);
    partial_k<<<NB, 256>>>(cnt, bsum);
    scanb_k<<<1, 256>>>(bsum);
    rowptr_k<<<NB, 256>>>(cnt, bsum, rowptr, cur, dinv);
    fill_k<<<(NE + T - 1) / T, T>>>(e_src, e_dst, dinv, cur, edge);

    // pre MLP
    tgemm_k<<<g128, T>>>(x, w_pre1, h0, NN, H);
    biasact_k<<<(NN * H / 4 + T - 1) / T, T>>>(h0, b_pre1);
    tgemm_k<<<g128, T>>>(h0, w_pre2, h1, NN, H);
    biasact_k<<<(NN * H / 4 + T - 1) / T, T>>>(h1, b_pre2);

    // ---- layer 0 ----
    tgemm_k<<<g128, T>>>(h1, w_gcn0, hw, NN, H);
    agg_k<<<(NN * 32 + T - 1) / T, T>>>(rowptr, edge, hw, dinv, b_gcn0, gcn);
    tgemm2_k<<<g384x2, T>>>(gcn, wih0, gi, prev0, whh0, gh, NN, H3);
    gru_k<<<(NN * H + T - 1) / T, T>>>(gi, gh, bih0, bhh0, prev0, emb0);

    // ---- layer 1 ----
    tgemm_k<<<g128, T>>>(emb0, w_gcn1, hw, NN, H);
    agg_k<<<(NN * 32 + T - 1) / T, T>>>(rowptr, edge, hw, dinv, b_gcn1, gcn);
    tgemm2_k<<<g384x2, T>>>(gcn, wih1, gi, prev1, whh1, gh, NN, H3);
    gru_k<<<(NN * H + T - 1) / T, T>>>(gi, gh, bih1, bhh1, prev1, emb1);

    // post head
    post_k<<<(NN * 32 + T - 1) / T, T>>>(emb1, w_post, b_post, out);
}